// round 2
// baseline (speedup 1.0000x reference)
#include <cuda_runtime.h>
#include <math.h>

// Problem constants (fixed shapes from setup_inputs)
#define N_   16
#define C_   64
#define H_   256
#define W_   256
#define HO_  254       // conv output H (valid)
#define WO_  254
#define PH_  127       // pooled H
#define PW_  127

// Tiling
#define TH 8           // conv-output rows per block (even)
#define TW 32          // conv-output cols per block (even, mult of 4)
#define CO_CHUNK 32    // output channels resident in smem at once
#define THREADS 256

// Shared memory layout
#define IN_ROWPITCH 36               // (TW+2)=34 padded to mult of 4 for float4 LDS
#define IN_ROWS     (TH + 2)         // 10
#define IN_PLANE    (IN_ROWS * IN_ROWPITCH)   // 360 floats per ci
#define IN_ELEMS    (C_ * IN_PLANE)           // 23040 floats
#define W_ELEMS     (C_ * 9 * CO_CHUNK)       // 18432 floats
#define SMEM_BYTES  ((IN_ELEMS + W_ELEMS) * 4)  // 165888 B

// ---- packed fp32x2 helpers (Blackwell FFMA2 path; ptxas never auto-fuses) ----
__device__ __forceinline__ unsigned long long f2_dup(float v) {
    unsigned long long r;
    unsigned int u = __float_as_uint(v);
    asm("mov.b64 %0, {%1, %2};" : "=l"(r) : "r"(u), "r"(u));
    return r;
}
__device__ __forceinline__ unsigned long long f2_pack(float lo, float hi) {
    unsigned long long r;
    asm("mov.b64 %0, {%1, %2};" : "=l"(r)
        : "r"(__float_as_uint(lo)), "r"(__float_as_uint(hi)));
    return r;
}
__device__ __forceinline__ void f2_fma(unsigned long long& d,
                                       unsigned long long a,
                                       unsigned long long b) {
    asm("fma.rn.f32x2 %0, %1, %2, %0;" : "+l"(d) : "l"(a), "l"(b));
}
__device__ __forceinline__ void f2_unpack(unsigned long long v, float& lo, float& hi) {
    asm("mov.b64 {%0, %1}, %2;" : "=f"(lo), "=f"(hi) : "l"(v));
}

__global__ __launch_bounds__(THREADS, 1)
void conv_hsw_pool_mish_kernel(const float* __restrict__ x,
                               const float* __restrict__ wgt,
                               const float* __restrict__ bias,
                               float* __restrict__ out)
{
    extern __shared__ float smem[];
    float* in_s = smem;              // [C_][IN_ROWS][IN_ROWPITCH]
    float* w_s  = smem + IN_ELEMS;   // [(ci*9+tap)*CO_CHUNK + col]

    const int n   = blockIdx.z;
    const int h0  = blockIdx.y * TH;   // conv-output row base (even)
    const int w0  = blockIdx.x * TW;   // conv-output col base (even)
    const int tid = threadIdx.x;

    // ---- Stage input tile: rows h0..h0+9, cols w0..w0+35 (zero-clamped) ----
    const float* xn = x + (size_t)n * (C_ * H_ * W_);
    for (int idx = tid; idx < IN_ELEMS; idx += THREADS) {
        int ci  = idx / IN_PLANE;
        int rem = idx - ci * IN_PLANE;
        int r   = rem / IN_ROWPITCH;
        int c   = rem - r * IN_ROWPITCH;
        int gh = h0 + r;
        int gw = w0 + c;
        float v = 0.0f;
        if (gh < H_ && gw < W_)
            v = xn[(size_t)ci * (H_ * W_) + gh * W_ + gw];
        in_s[idx] = v;
    }

    // ---- Thread mapping: 2(h) x 4(w) conv pixels x 4 co per thread ----
    const int wq  = tid & 7;          // w quad index (0..7)  -> wl0 = wq*4
    const int hp  = (tid >> 3) & 3;   // h pair index (0..3)  -> hl0 = hp*2
    const int cg  = tid >> 5;         // co group (0..7), 4 co each
    const int wl0 = wq * 4;
    const int hl0 = hp * 2;

    for (int cc = 0; cc < C_; cc += CO_CHUNK) {
        __syncthreads();  // protect w_s against previous chunk's readers
                          // (first pass: also fences in_s staging)

        // ---- Stage weight chunk, transposed: w_s[(ci*9+tap)*32 + col] ----
        for (int idx = tid; idx < W_ELEMS; idx += THREADS) {
            int col = idx & (CO_CHUNK - 1);
            int t2  = idx >> 5;             // ci*9 + tap  (CO_CHUNK==32)
            int ci  = t2 / 9;
            int tap = t2 - ci * 9;
            w_s[idx] = wgt[(size_t)(cc + col) * (C_ * 9) + ci * 9 + tap];
        }
        __syncthreads();

        // ---- Accumulate: [ro 2][co-pair 2][pixel 4] packed fp32x2 ----
        unsigned long long acc2[2][2][4];
        #pragma unroll
        for (int a = 0; a < 2; a++)
            #pragma unroll
            for (int b = 0; b < 2; b++)
                #pragma unroll
                for (int p = 0; p < 4; p++)
                    acc2[a][b][p] = 0ull;

        const float* inp = in_s + hl0 * IN_ROWPITCH + wl0;
        const float* wp  = w_s + cg * 4;

        #pragma unroll 2
        for (int ci = 0; ci < C_; ci++) {
            // 4 input rows x 6 cols, vectorized LDS; duplicate into both f32x2 lanes
            unsigned long long xd[4][6];
            #pragma unroll
            for (int r = 0; r < 4; r++) {
                float4 a4 = *reinterpret_cast<const float4*>(inp + r * IN_ROWPITCH);
                float2 b2 = *reinterpret_cast<const float2*>(inp + r * IN_ROWPITCH + 4);
                xd[r][0] = f2_dup(a4.x); xd[r][1] = f2_dup(a4.y);
                xd[r][2] = f2_dup(a4.z); xd[r][3] = f2_dup(a4.w);
                xd[r][4] = f2_dup(b2.x); xd[r][5] = f2_dup(b2.y);
            }
            #pragma unroll
            for (int tap = 0; tap < 9; tap++) {
                float4 wv = *reinterpret_cast<const float4*>(wp + tap * CO_CHUNK);
                unsigned long long w01 = f2_pack(wv.x, wv.y);
                unsigned long long w23 = f2_pack(wv.z, wv.w);
                const int kh = tap / 3;
                const int kw = tap - kh * 3;
                #pragma unroll
                for (int ro = 0; ro < 2; ro++) {
                    #pragma unroll
                    for (int p = 0; p < 4; p++) {
                        unsigned long long xx = xd[ro + kh][kw + p];
                        f2_fma(acc2[ro][0][p], w01, xx);
                        f2_fma(acc2[ro][1][p], w23, xx);
                    }
                }
            }
            inp += IN_PLANE;
            wp  += 9 * CO_CHUNK;
        }

        // ---- Unpack accumulators: acc[ro][co][p] ----
        float acc[2][4][4];
        #pragma unroll
        for (int ro = 0; ro < 2; ro++)
            #pragma unroll
            for (int pr = 0; pr < 2; pr++)
                #pragma unroll
                for (int p = 0; p < 4; p++)
                    f2_unpack(acc2[ro][pr][p], acc[ro][2 * pr][p], acc[ro][2 * pr + 1][p]);

        // ---- Epilogue: bias, -0.5, hardswish, 2x2 maxpool (in-thread), mish ----
        const int ph  = (h0 + hl0) >> 1;   // this thread's single pooled row
        const int pw0 = (w0 + wl0) >> 1;   // two pooled cols: pw0, pw0+1
        if (ph < PH_) {
            #pragma unroll
            for (int co = 0; co < 4; co++) {
                const int oc = cc + cg * 4 + co;
                const float b = bias[oc] - 0.5f;
                float hs[2][4];
                #pragma unroll
                for (int ro = 0; ro < 2; ro++) {
                    #pragma unroll
                    for (int p = 0; p < 4; p++) {
                        float v  = acc[ro][co][p] + b;
                        float cl = fminf(fmaxf(v + 3.0f, 0.0f), 6.0f);
                        hs[ro][p] = v * cl * (1.0f / 6.0f);
                    }
                }
                float* op = out + ((size_t)n * C_ + oc) * (PH_ * PW_) + ph * PW_;
                #pragma unroll
                for (int q = 0; q < 2; q++) {
                    const int pw = pw0 + q;
                    if (pw < PW_) {
                        float m = fmaxf(fmaxf(hs[0][2 * q], hs[0][2 * q + 1]),
                                        fmaxf(hs[1][2 * q], hs[1][2 * q + 1]));
                        // mish(m) = m * tanh(softplus(m)); m >= -0.375 here
                        float sp = (m > 20.0f) ? m : log1pf(expf(m));
                        op[pw] = m * tanhf(sp);
                    }
                }
            }
        }
    }
}

extern "C" void kernel_launch(void* const* d_in, const int* in_sizes, int n_in,
                              void* d_out, int out_size)
{
    (void)in_sizes; (void)n_in; (void)out_size;
    const float* x    = (const float*)d_in[0];   // [16,64,256,256] f32
    const float* wgt  = (const float*)d_in[1];   // [64,64,3,3]     f32
    const float* bias = (const float*)d_in[2];   // [64]            f32
    float* out        = (float*)d_out;           // [16,64,127,127] f32

    // Opt into >48KB dynamic smem (idempotent; host-side, capture-safe).
    cudaFuncSetAttribute(conv_hsw_pool_mish_kernel,
                         cudaFuncAttributeMaxDynamicSharedMemorySize, SMEM_BYTES);

    dim3 grid((WO_ + TW - 1) / TW,   // 8
              (HO_ + TH - 1) / TH,   // 32
              N_);                   // 16
    conv_hsw_pool_mish_kernel<<<grid, THREADS, SMEM_BYTES>>>(x, wgt, bias, out);
}

// round 6
// speedup vs baseline: 1.9632x; 1.9632x over previous
#include <cuda_runtime.h>
#include <cuda_bf16.h>
#include <math.h>
#include <stdint.h>

#define THREADS 256

// ---------------- smem layout (bytes) ----------------
#define SMEM_BIAS 0                       // 64 floats (bias - 0.5)
#define SMEM_BF   256                     // B fragments
#define BF_LANEPITCH 144                  // 128B payload + 16B pad; 36 words = 4 (mod 32)
#define BF_KPITCH   (32 * BF_LANEPITCH)   // 4608 per kstep
#define BF_BYTES    (36 * BF_KPITCH)      // 165888
#define SMEM_XHI  (SMEM_BF + BF_BYTES)    // 166144 (16B aligned)
#define X_PITCH   144                     // bytes per spatial site: 64 ci bf16 + pad;
                                          // 36 words = 4 (mod 32) -> bank = 4g+q, conflict-free
#define X_BYTES   (180 * X_PITCH)         // 25920 (10 rows x 18 cols sites)
#define SMEM_XLO  (SMEM_XHI + X_BYTES)    // 192064
#define SMEM_TOTAL (SMEM_XLO + X_BYTES)   // 217984  (< 227KB cap)

static __device__ __forceinline__ void mma16816(float* c, const uint32_t* a, const uint32_t* b) {
    asm volatile(
        "mma.sync.aligned.m16n8k16.row.col.f32.bf16.bf16.f32 "
        "{%0,%1,%2,%3}, {%4,%5,%6,%7}, {%8,%9}, {%0,%1,%2,%3};"
        : "+f"(c[0]), "+f"(c[1]), "+f"(c[2]), "+f"(c[3])
        : "r"(a[0]), "r"(a[1]), "r"(a[2]), "r"(a[3]), "r"(b[0]), "r"(b[1]));
}

static __device__ __forceinline__ uint32_t packbf(__nv_bfloat16 lo, __nv_bfloat16 hi) {
    return (uint32_t)__bfloat16_as_ushort(lo) | ((uint32_t)__bfloat16_as_ushort(hi) << 16);
}

static __device__ __forceinline__ float mishf(float m) {
    // mish(m) = m * tanh(softplus(m)) = m * (e^2+2e)/(e^2+2e+2), e = exp(m)
    float e = __expf(m);
    float nmr = e * (e + 2.0f);
    float t = nmr / (nmr + 2.0f);
    return (m > 15.0f) ? m : m * t;   // large-m branch avoids inf/inf
}

__global__ __launch_bounds__(THREADS, 1)
void conv_mma_kernel(const float* __restrict__ x,
                     const float* __restrict__ wgt,
                     const float* __restrict__ bias,
                     float* __restrict__ out)
{
    extern __shared__ char smem[];
    const int tid = threadIdx.x;
    const int w   = tid >> 5;
    const int l   = tid & 31;
    const int g   = l >> 2;      // lane group: mma A/C row, B n-index
    const int q   = l & 3;       // mma k-pair selector; C n-pair selector
    const int h   = w & 1;       // N-group: co 32h..32h+31
    const int v   = w >> 1;      // M-group: pixel cols 4v..4v+3

    // ---- bias - 0.5 ----
    if (tid < 64)
        reinterpret_cast<float*>(smem + SMEM_BIAS)[tid] = bias[tid] - 0.5f;

    // ---- stage B (weights) in mma fragment order, split hi/lo ----
    // entry(kstep ks, lane ll, nb): co = nb*8 + (ll>>2), ci = (ks&3)*16 + (ll&3)*2,
    // tap = ks>>2; b0 = w(ci,ci+1), b1 = w(ci+8,ci+9)   [k' = tap*64 + ci]
    for (int idx = tid; idx < 9216; idx += THREADS) {
        int ks  = idx >> 8;
        int rem = idx & 255;
        int ll  = rem >> 3;
        int nb  = rem & 7;
        int co  = nb * 8 + (ll >> 2);
        int ci  = ((ks & 3) << 4) + ((ll & 3) << 1);
        int tap = ks >> 2;
        const float* wp = wgt + co * 576 + ci * 9 + tap;
        float w00 = wp[0], w01 = wp[9], w10 = wp[72], w11 = wp[81];
        __nv_bfloat16 h00 = __float2bfloat16(w00), h01 = __float2bfloat16(w01);
        __nv_bfloat16 h10 = __float2bfloat16(w10), h11 = __float2bfloat16(w11);
        __nv_bfloat16 l00 = __float2bfloat16(w00 - __bfloat162float(h00));
        __nv_bfloat16 l01 = __float2bfloat16(w01 - __bfloat162float(h01));
        __nv_bfloat16 l10 = __float2bfloat16(w10 - __bfloat162float(h10));
        __nv_bfloat16 l11 = __float2bfloat16(w11 - __bfloat162float(h11));
        char* p = smem + SMEM_BF + ks * BF_KPITCH + ll * BF_LANEPITCH + nb * 8;
        *reinterpret_cast<uint32_t*>(p)      = packbf(h00, h01);
        *reinterpret_cast<uint32_t*>(p + 4)  = packbf(h10, h11);
        *reinterpret_cast<uint32_t*>(p + 64) = packbf(l00, l01);
        *reinterpret_cast<uint32_t*>(p + 68) = packbf(l10, l11);
    }
    __syncthreads();

    // hoist per-thread bias values (co0 = h*32 + nbi*8 + q*2)
    float bsr[4][2];
    {
        const float* bs = reinterpret_cast<const float*>(smem + SMEM_BIAS);
        #pragma unroll
        for (int nbi = 0; nbi < 4; nbi++) {
            int co0 = h * 32 + nbi * 8 + q * 2;
            bsr[nbi][0] = bs[co0];
            bsr[nbi][1] = bs[co0 + 1];
        }
    }

    for (int t = 0; t < 4; t++) {
        const int gt  = blockIdx.x * 4 + t;
        const int n   = gt >> 9;
        const int rem = gt & 511;
        const int h0  = (rem >> 4) << 3;    // conv-output row base (8 rows)
        const int w0  = (rem & 15) << 4;    // conv-output col base (16 cols)

        if (t) __syncthreads();             // prior tile's k-loop readers done

        // ---- stage x tile [64ci][10][18] -> hi/lo bf16, [spat][ci] pitch 144B ----
        {
            const float* xn = x + ((size_t)n << 22);   // n * 64 * 65536
            for (int idx = tid; idx < 11520; idx += THREADS) {
                int ci = idx / 180;
                int r2 = idx - ci * 180;
                int rr = r2 / 18;
                int cc = r2 - rr * 18;
                int gh = h0 + rr, gw = w0 + cc;
                float vv = (gh < 256 && gw < 256) ? xn[(ci << 16) + (gh << 8) + gw] : 0.0f;
                __nv_bfloat16 hb = __float2bfloat16(vv);
                __nv_bfloat16 lb = __float2bfloat16(vv - __bfloat162float(hb));
                int so = (rr * 18 + cc) * X_PITCH + ci * 2;
                *reinterpret_cast<__nv_bfloat16*>(smem + SMEM_XHI + so) = hb;
                *reinterpret_cast<__nv_bfloat16*>(smem + SMEM_XLO + so) = lb;
            }
        }
        __syncthreads();

        // ---- main K loop: 9 taps x 4 ci-blocks, 3-term split-bf16 mma ----
        float acc[2][4][4];
        #pragma unroll
        for (int a = 0; a < 2; a++)
            #pragma unroll
            for (int b = 0; b < 4; b++)
                #pragma unroll
                for (int cI = 0; cI < 4; cI++)
                    acc[a][b][cI] = 0.0f;

        for (int tap = 0; tap < 9; tap++) {
            const int kh = tap / 3;
            const int kw = tap - kh * 3;
            int sA[2];
            #pragma unroll
            for (int mb = 0; mb < 2; mb++)
                sA[mb] = ((g + kh) * 18 + (4 * v + 2 * mb + kw)) * X_PITCH;

            #pragma unroll
            for (int cb = 0; cb < 4; cb++) {
                const int ks4 = tap * 4 + cb;
                const char* bp = smem + SMEM_BF + ks4 * BF_KPITCH + l * BF_LANEPITCH + h * 32;
                uint4 bh01 = *reinterpret_cast<const uint4*>(bp);
                uint4 bh23 = *reinterpret_cast<const uint4*>(bp + 16);
                uint4 bl01 = *reinterpret_cast<const uint4*>(bp + 64);
                uint4 bl23 = *reinterpret_cast<const uint4*>(bp + 80);
                uint32_t BH[4][2] = {{bh01.x, bh01.y}, {bh01.z, bh01.w},
                                     {bh23.x, bh23.y}, {bh23.z, bh23.w}};
                uint32_t BL[4][2] = {{bl01.x, bl01.y}, {bl01.z, bl01.w},
                                     {bl23.x, bl23.y}, {bl23.z, bl23.w}};
                const int cio = cb * 32 + q * 4;   // byte offset of this thread's ci pair

                #pragma unroll
                for (int mb = 0; mb < 2; mb++) {
                    const char* xh = smem + SMEM_XHI + sA[mb] + cio;
                    const char* xl = smem + SMEM_XLO + sA[mb] + cio;
                    uint32_t A[4], AL[4];
                    A[0]  = *reinterpret_cast<const uint32_t*>(xh);            // row g,   k0
                    A[1]  = *reinterpret_cast<const uint32_t*>(xh + X_PITCH);  // row g+8, k0
                    A[2]  = *reinterpret_cast<const uint32_t*>(xh + 16);       // row g,   k0+8
                    A[3]  = *reinterpret_cast<const uint32_t*>(xh + X_PITCH + 16);
                    AL[0] = *reinterpret_cast<const uint32_t*>(xl);
                    AL[1] = *reinterpret_cast<const uint32_t*>(xl + X_PITCH);
                    AL[2] = *reinterpret_cast<const uint32_t*>(xl + 16);
                    AL[3] = *reinterpret_cast<const uint32_t*>(xl + X_PITCH + 16);
                    #pragma unroll
                    for (int nbi = 0; nbi < 4; nbi++) {
                        mma16816(acc[mb][nbi], A,  BH[nbi]);   // hi*hi
                        mma16816(acc[mb][nbi], AL, BH[nbi]);   // lo*hi
                        mma16816(acc[mb][nbi], A,  BL[nbi]);   // hi*lo
                    }
                }
            }
        }

        // ---- epilogue: bias, hardswish, 2x2 pool (in-thread cols + shfl rows), mish ----
        const int ph = (h0 >> 1) + (g >> 1);
        const bool wr = ((g & 1) == 0) && (ph < 127);
        float* outn = out + (size_t)n * 64 * 16129;

        #pragma unroll
        for (int mb = 0; mb < 2; mb++) {
            const int pw = (w0 >> 1) + 2 * v + mb;
            const bool ok = wr && (pw < 127);
            #pragma unroll
            for (int nbi = 0; nbi < 4; nbi++) {
                const int co0 = h * 32 + nbi * 8 + q * 2;
                float u0 = acc[mb][nbi][0] + bsr[nbi][0];   // pix col even, co0
                float u1 = acc[mb][nbi][1] + bsr[nbi][1];   // pix col even, co0+1
                float u2 = acc[mb][nbi][2] + bsr[nbi][0];   // pix col odd,  co0
                float u3 = acc[mb][nbi][3] + bsr[nbi][1];   // pix col odd,  co0+1
                float s0 = u0 * fminf(fmaxf(u0 + 3.0f, 0.0f), 6.0f) * (1.0f / 6.0f);
                float s1 = u1 * fminf(fmaxf(u1 + 3.0f, 0.0f), 6.0f) * (1.0f / 6.0f);
                float s2 = u2 * fminf(fmaxf(u2 + 3.0f, 0.0f), 6.0f) * (1.0f / 6.0f);
                float s3 = u3 * fminf(fmaxf(u3 + 3.0f, 0.0f), 6.0f) * (1.0f / 6.0f);
                float p0 = fmaxf(s0, s2);                   // col max (co0)
                float p1 = fmaxf(s1, s3);                   // col max (co0+1)
                float m0 = fmaxf(p0, __shfl_xor_sync(0xFFFFFFFFu, p0, 4));  // row max
                float m1 = fmaxf(p1, __shfl_xor_sync(0xFFFFFFFFu, p1, 4));
                if (ok) {
                    outn[(size_t)co0 * 16129 + ph * 127 + pw]       = mishf(m0);
                    outn[(size_t)(co0 + 1) * 16129 + ph * 127 + pw] = mishf(m1);
                }
            }
        }
    }
}

extern "C" void kernel_launch(void* const* d_in, const int* in_sizes, int n_in,
                              void* d_out, int out_size)
{
    (void)in_sizes; (void)n_in; (void)out_size;
    const float* x    = (const float*)d_in[0];   // [16,64,256,256] f32
    const float* wgt  = (const float*)d_in[1];   // [64,64,3,3]     f32
    const float* bias = (const float*)d_in[2];   // [64]            f32
    float* out        = (float*)d_out;           // [16,64,127,127] f32

    cudaFuncSetAttribute(conv_mma_kernel,
                         cudaFuncAttributeMaxDynamicSharedMemorySize, SMEM_TOTAL);

    // 8192 tiles (16 n x 32 row-tiles x 16 col-tiles), 4 tiles per CTA
    conv_mma_kernel<<<2048, THREADS, SMEM_TOTAL>>>(x, wgt, bias, out);
}

// round 7
// speedup vs baseline: 3.4532x; 1.7590x over previous
#include <cuda_runtime.h>
#include <cuda_fp16.h>
#include <math.h>
#include <stdint.h>

#define THREADS 512

// ---------------- smem layout (bytes) ----------------
#define SMEM_BIAS 0                        // 64 floats (bias - 0.5)
#define SMEM_BF   256                      // B fragments, fp16 hi/lo
// per (kstep, lane): 128B payload = 64B hi (nb 0..7) + 64B lo, chunk-XOR swizzled
#define BF_KPITCH 4096                     // 32 lanes * 128B
#define BF_BYTES  (36 * BF_KPITCH)         // 147456
#define SMEM_XA   (SMEM_BF + BF_BYTES)     // 147712
#define X_PITCH   136                      // 34 words; 18*34 = 4 (mod 32) -> A banks 4g+q
#define X_BYTES   (180 * X_PITCH)          // 24480 (10 rows x 18 cols sites, 64ci fp16)
#define SMEM_XB   (SMEM_XA + X_BYTES)      // 172192
#define SMEM_TOTAL (SMEM_XB + X_BYTES)     // 196672  (< 227KB cap)

static __device__ __forceinline__ void mma16816(float* c, const uint32_t* a, const uint32_t* b) {
    asm volatile(
        "mma.sync.aligned.m16n8k16.row.col.f32.f16.f16.f32 "
        "{%0,%1,%2,%3}, {%4,%5,%6,%7}, {%8,%9}, {%0,%1,%2,%3};"
        : "+f"(c[0]), "+f"(c[1]), "+f"(c[2]), "+f"(c[3])
        : "r"(a[0]), "r"(a[1]), "r"(a[2]), "r"(a[3]), "r"(b[0]), "r"(b[1]));
}

static __device__ __forceinline__ uint32_t packh(__half lo, __half hi) {
    return (uint32_t)__half_as_ushort(lo) | ((uint32_t)__half_as_ushort(hi) << 16);
}

static __device__ __forceinline__ void barg(int id) {   // group-local named barrier (256 thr)
    asm volatile("bar.sync %0, 256;" :: "r"(id) : "memory");
}

static __device__ __forceinline__ float mishf(float m) {
    // mish(m) = m * (e^2+2e)/(e^2+2e+2), e = exp(m); large-m guard avoids inf/inf
    float e = __expf(m);
    float nmr = e * (e + 2.0f);
    return (m > 15.0f) ? m : m * (nmr / (nmr + 2.0f));
}

__global__ __launch_bounds__(THREADS, 1)
void conv_mma_kernel(const float* __restrict__ x,
                     const float* __restrict__ wgt,
                     const float* __restrict__ bias,
                     float* __restrict__ out)
{
    extern __shared__ char smem[];
    const int tid  = threadIdx.x;
    const int tg   = tid >> 8;        // tile group 0/1
    const int t256 = tid & 255;       // id within group
    const int w8   = t256 >> 5;       // warp within group (0..7)
    const int l    = tid & 31;
    const int g    = l >> 2;          // mma A/C row group
    const int q    = l & 3;           // mma k-pair / C n-pair selector
    const int s7   = l & 7;           // B chunk-swizzle key
    const int h    = w8 & 1;          // N half: co 32h..32h+31
    const int v    = w8 >> 1;         // M group: pixel cols 4v..4v+3
    char* const xbase = smem + (tg ? SMEM_XB : SMEM_XA);

    // ---- bias - 0.5 ----
    if (tid < 64)
        reinterpret_cast<float*>(smem + SMEM_BIAS)[tid] = bias[tid] - 0.5f;

    // ---- stage B (weights) fp16 hi/lo in mma fragment order, XOR-chunk swizzle ----
    // entry(ks, ll, nb): co = nb*8 + (ll>>2), ci = (ks&3)*16 + (ll&3)*2, tap = ks>>2
    for (int idx = tid; idx < 9216; idx += THREADS) {
        int ks  = idx >> 8;
        int rem = idx & 255;
        int ll  = rem >> 3;
        int nb  = rem & 7;
        int co  = nb * 8 + (ll >> 2);
        int ci  = ((ks & 3) << 4) + ((ll & 3) << 1);
        int tap = ks >> 2;
        const float* wp = wgt + co * 576 + ci * 9 + tap;
        float w00 = wp[0], w01 = wp[9], w10 = wp[72], w11 = wp[81];
        __half h00 = __float2half(w00), h01 = __float2half(w01);
        __half h10 = __float2half(w10), h11 = __float2half(w11);
        __half l00 = __float2half(w00 - __half2float(h00));
        __half l01 = __float2half(w01 - __half2float(h01));
        __half l10 = __float2half(w10 - __half2float(h10));
        __half l11 = __float2half(w11 - __half2float(h11));
        char* lane = smem + SMEM_BF + ks * BF_KPITCH + ll * 128;
        int key = ll & 7;
        int jhi = (nb >> 1) ^ key;          // hi chunk (16B)
        int jlo = (4 + (nb >> 1)) ^ key;    // lo chunk
        int o   = (nb & 1) * 8;
        *reinterpret_cast<uint32_t*>(lane + jhi * 16 + o)     = packh(h00, h01);
        *reinterpret_cast<uint32_t*>(lane + jhi * 16 + o + 4) = packh(h10, h11);
        *reinterpret_cast<uint32_t*>(lane + jlo * 16 + o)     = packh(l00, l01);
        *reinterpret_cast<uint32_t*>(lane + jlo * 16 + o + 4) = packh(l10, l11);
    }
    __syncthreads();

    // per-thread physical 16B-chunk offsets for this warp's B reads (constant)
    const int oh0 = (((2 * h)     ^ s7) << 4);
    const int oh1 = (((2 * h + 1) ^ s7) << 4);
    const int ol0 = (((4 + 2 * h) ^ s7) << 4);
    const int ol1 = (((5 + 2 * h) ^ s7) << 4);

    // hoist bias (co0 = h*32 + nbi*8 + q*2)
    float bsr[4][2];
    {
        const float* bs = reinterpret_cast<const float*>(smem + SMEM_BIAS);
        #pragma unroll
        for (int nbi = 0; nbi < 4; nbi++) {
            int co0 = h * 32 + nbi * 8 + q * 2;
            bsr[nbi][0] = bs[co0];
            bsr[nbi][1] = bs[co0 + 1];
        }
    }

    const int barid = 1 + tg;   // group-local barrier id

    for (int it = 0; it < 4; it++) {
        const int gt  = blockIdx.x * 8 + it * 2 + tg;
        const int n   = gt >> 9;
        const int rem = gt & 511;
        const int h0  = (rem >> 4) << 3;    // conv-output row base
        const int w0  = (rem & 15) << 4;    // conv-output col base

        barg(barid);   // prior tile's X readers done (group-local)

        // ---- stage x tile [64ci][10][18] -> fp16, [site][ci], pitch 136B ----
        {
            const float* xn = x + ((size_t)n << 22);
            for (int idx = t256; idx < 11520; idx += 256) {
                int ci = idx / 180;
                int r2 = idx - ci * 180;
                int rr = r2 / 18;
                int cc = r2 - rr * 18;
                int gh = h0 + rr, gw = w0 + cc;
                float vv = (gh < 256 && gw < 256) ? xn[(ci << 16) + (gh << 8) + gw] : 0.0f;
                *reinterpret_cast<__half*>(xbase + (rr * 18 + cc) * X_PITCH + ci * 2) =
                    __float2half(vv);
            }
        }
        barg(barid);

        // ---- main K loop: 9 taps x 4 ci-blocks, 2-term (A * (Bh + Bl)) ----
        float acc[2][4][4];
        #pragma unroll
        for (int a = 0; a < 2; a++)
            #pragma unroll
            for (int b = 0; b < 4; b++)
                #pragma unroll
                for (int cI = 0; cI < 4; cI++)
                    acc[a][b][cI] = 0.0f;

        for (int tap = 0; tap < 9; tap++) {
            const int kh = tap / 3;
            const int kw = tap - kh * 3;
            int sA[2];
            #pragma unroll
            for (int mb = 0; mb < 2; mb++)
                sA[mb] = ((g + kh) * 18 + (4 * v + 2 * mb + kw)) * X_PITCH;

            #pragma unroll
            for (int cb = 0; cb < 4; cb++) {
                const char* lane = smem + SMEM_BF + (tap * 4 + cb) * BF_KPITCH + l * 128;
                uint4 bh01 = *reinterpret_cast<const uint4*>(lane + oh0);
                uint4 bh23 = *reinterpret_cast<const uint4*>(lane + oh1);
                uint4 bl01 = *reinterpret_cast<const uint4*>(lane + ol0);
                uint4 bl23 = *reinterpret_cast<const uint4*>(lane + ol1);
                uint32_t BH[4][2] = {{bh01.x, bh01.y}, {bh01.z, bh01.w},
                                     {bh23.x, bh23.y}, {bh23.z, bh23.w}};
                uint32_t BL[4][2] = {{bl01.x, bl01.y}, {bl01.z, bl01.w},
                                     {bl23.x, bl23.y}, {bl23.z, bl23.w}};
                const int cio = cb * 32 + q * 4;

                #pragma unroll
                for (int mb = 0; mb < 2; mb++) {
                    const char* xh = xbase + sA[mb] + cio;
                    uint32_t A[4];
                    A[0] = *reinterpret_cast<const uint32_t*>(xh);                // row g,   k0
                    A[1] = *reinterpret_cast<const uint32_t*>(xh + X_PITCH);      // row g+8, k0
                    A[2] = *reinterpret_cast<const uint32_t*>(xh + 16);           // row g,   k0+8
                    A[3] = *reinterpret_cast<const uint32_t*>(xh + X_PITCH + 16); // row g+8, k0+8
                    #pragma unroll
                    for (int nbi = 0; nbi < 4; nbi++) {
                        mma16816(acc[mb][nbi], A, BH[nbi]);   // A * B_hi
                        mma16816(acc[mb][nbi], A, BL[nbi]);   // A * B_lo
                    }
                }
            }
        }

        // ---- epilogue: bias, hardswish, 2x2 pool (in-thread cols + shfl rows), mish ----
        const int ph = (h0 >> 1) + (g >> 1);
        const bool wr = ((g & 1) == 0) && (ph < 127);
        float* outn = out + (size_t)n * 64 * 16129;

        #pragma unroll
        for (int mb = 0; mb < 2; mb++) {
            const int pw = (w0 >> 1) + 2 * v + mb;
            const bool ok = wr && (pw < 127);
            #pragma unroll
            for (int nbi = 0; nbi < 4; nbi++) {
                const int co0 = h * 32 + nbi * 8 + q * 2;
                float u0 = acc[mb][nbi][0] + bsr[nbi][0];   // col even, co0
                float u1 = acc[mb][nbi][1] + bsr[nbi][1];   // col even, co0+1
                float u2 = acc[mb][nbi][2] + bsr[nbi][0];   // col odd,  co0
                float u3 = acc[mb][nbi][3] + bsr[nbi][1];   // col odd,  co0+1
                float s0 = u0 * fminf(fmaxf(u0 + 3.0f, 0.0f), 6.0f) * (1.0f / 6.0f);
                float s1 = u1 * fminf(fmaxf(u1 + 3.0f, 0.0f), 6.0f) * (1.0f / 6.0f);
                float s2 = u2 * fminf(fmaxf(u2 + 3.0f, 0.0f), 6.0f) * (1.0f / 6.0f);
                float s3 = u3 * fminf(fmaxf(u3 + 3.0f, 0.0f), 6.0f) * (1.0f / 6.0f);
                float p0 = fmaxf(s0, s2);
                float p1 = fmaxf(s1, s3);
                float m0 = fmaxf(p0, __shfl_xor_sync(0xFFFFFFFFu, p0, 4));
                float m1 = fmaxf(p1, __shfl_xor_sync(0xFFFFFFFFu, p1, 4));
                if (ok) {
                    outn[(size_t)co0 * 16129 + ph * 127 + pw]       = mishf(m0);
                    outn[(size_t)(co0 + 1) * 16129 + ph * 127 + pw] = mishf(m1);
                }
            }
        }
    }
}

extern "C" void kernel_launch(void* const* d_in, const int* in_sizes, int n_in,
                              void* d_out, int out_size)
{
    (void)in_sizes; (void)n_in; (void)out_size;
    const float* x    = (const float*)d_in[0];   // [16,64,256,256] f32
    const float* wgt  = (const float*)d_in[1];   // [64,64,3,3]     f32
    const float* bias = (const float*)d_in[2];   // [64]            f32
    float* out        = (float*)d_out;           // [16,64,127,127] f32

    cudaFuncSetAttribute(conv_mma_kernel,
                         cudaFuncAttributeMaxDynamicSharedMemorySize, SMEM_TOTAL);

    // 8192 tiles, 8 per CTA (2 concurrent groups x 4 iterations)
    conv_mma_kernel<<<1024, THREADS, SMEM_TOTAL>>>(x, wgt, bias, out);
}